// round 12
// baseline (speedup 1.0000x reference)
#include <cuda_runtime.h>
#include <cstdint>

#define NN 50000
#define FF 128
#define DD 256
#define EE 800000
#define GG 128
#define BN_EPS 1e-5f
#define NBLK 148
#define NTHR 1024
#define NPAD 50048         // 391*128, covers all GEMM tile rows

// ---------------- static scratch ----------------
// activations, packed split-bf16: [row][K/2] u32 (2 bf16 per u32)
__device__ uint32_t g_ahi[(size_t)NPAD * 128];
__device__ uint32_t g_alo[(size_t)NPAD * 128];
__device__ uint32_t g_hhi[(size_t)NPAD * 128];
__device__ uint32_t g_hlo[(size_t)NPAD * 128];
__device__ float    g_h2 [(size_t)NN * DD];
__device__ float    g_stats[2 * DD];
__device__ float    g_scsh[2 * DD];
__device__ int      g_idx64;
__device__ uint32_t g_bhi[6 * 256 * 128];
__device__ uint32_t g_blo[6 * 256 * 128];
__device__ int      g_deg[NN];
__device__ int      g_off[NN + 1];
__device__ int      g_wp [NN];
__device__ int      g_srcs[EE];
__device__ int      g_part2[NBLK];
__device__ unsigned g_bar[8];
__device__ unsigned g_done;

// ---------------- helpers ----------------
__device__ __forceinline__ void split2(float e, float o, uint32_t& hi, uint32_t& lo) {
    uint32_t h;
    asm("cvt.rn.bf16x2.f32 %0, %1, %2;" : "=r"(h) : "f"(o), "f"(e));
    float ef = __uint_as_float(h << 16);
    float of = __uint_as_float(h & 0xffff0000u);
    uint32_t l;
    asm("cvt.rn.bf16x2.f32 %0, %1, %2;" : "=r"(l) : "f"(o - of), "f"(e - ef));
    hi = h; lo = l;
}
__device__ __forceinline__ void mma_bf16(float* d, const uint32_t* a, const uint32_t* b) {
    asm volatile("mma.sync.aligned.m16n8k16.row.col.f32.bf16.bf16.f32 "
                 "{%0,%1,%2,%3}, {%4,%5,%6,%7}, {%8,%9}, {%0,%1,%2,%3};"
                 : "+f"(d[0]), "+f"(d[1]), "+f"(d[2]), "+f"(d[3])
                 : "r"(a[0]), "r"(a[1]), "r"(a[2]), "r"(a[3]), "r"(b[0]), "r"(b[1]));
}
__device__ __forceinline__ void ldsm4(uint32_t* r, uint32_t a) {
    asm volatile("ldmatrix.sync.aligned.m8n8.x4.shared.b16 {%0,%1,%2,%3}, [%4];"
                 : "=r"(r[0]), "=r"(r[1]), "=r"(r[2]), "=r"(r[3]) : "r"(a));
}
__device__ __forceinline__ void cp16(uint32_t dst, const void* src) {
    asm volatile("cp.async.cg.shared.global [%0], [%1], 16;" :: "r"(dst), "l"(src));
}
__device__ __forceinline__ uint32_t saddr(const void* p) {
    return (uint32_t)__cvta_generic_to_shared(p);
}
__device__ __forceinline__ int load_index(const void* p, long long i, int is64) {
    if (is64) return (int)((const long long*)p)[i];
    return ((const int*)p)[i];
}
__device__ __forceinline__ void gridbar(int i) {
    __syncthreads();
    if (threadIdx.x == 0) {
        unsigned* ctr = &g_bar[i];
        asm volatile("red.release.gpu.global.add.u32 [%0], 1;" :: "l"(ctr) : "memory");
        unsigned x;
        do {
            asm volatile("ld.acquire.gpu.global.u32 %0, [%1];" : "=r"(x) : "l"(ctr) : "memory");
        } while (x < NBLK);
    }
    __syncthreads();
}

// ---------------- 1: merged weight pre-split (+ idx dtype detect) ----------------
__global__ void convw_all_k(const float* w0, const float* w1, const float* w2,
                            const float* w3, const float* w4, const float* w5,
                            const int* ei) {
    int t = blockIdx.x * 256 + threadIdx.x;
    if (t >= 180224) {
        if (t == 180224) {
            int allz = 1;
            for (int j = 1; j < 512; j += 2)
                if (ei[j] != 0) { allz = 0; break; }
            g_idx64 = allz;
        }
        return;
    }
    const float* w; int kpc, loc, slot;
    if (t < 16384) { slot = 0; kpc = 64; loc = t; w = w0; }
    else {
        slot = 1 + (t - 16384) / 32768;
        loc  = (t - 16384) % 32768;
        kpc  = 128;
        w = (slot == 1) ? w1 : (slot == 2) ? w2 : (slot == 3) ? w3 : (slot == 4) ? w4 : w5;
    }
    int n = loc / kpc, kp = loc - n * kpc;
    float e = w[(2 * kp)     * 256 + n];
    float o = w[(2 * kp + 1) * 256 + n];
    uint32_t h, l;
    split2(e, o, h, l);
    g_bhi[slot * 32768 + n * kpc + kp] = h;
    g_blo[slot * 32768 + n * kpc + kp] = l;
}

// ---------------- 2: CSR build (cooperative) ----------------
__global__ void __launch_bounds__(NTHR)
csr_coop_k(const void* ei) {
    __shared__ int sm[512];
    __shared__ int bbase;
    const int b = blockIdx.x, t = threadIdx.x;
    const int gt = b * NTHR + t;
    const int GSTR = NBLK * NTHR;

    for (int i = gt; i < NN; i += GSTR) g_deg[i] = 0;
    gridbar(0);
    const int is64 = g_idx64;

    for (long long e = gt; e < EE; e += GSTR) {
        int dst = load_index(ei, EE + e, is64);
        atomicAdd(&g_deg[dst], 1);
    }
    gridbar(1);

    const int CH = (NN + NBLK - 1) / NBLK;
    const int c0 = b * CH;
    const int n  = min(NN, c0 + CH) - c0;
    int v = (t < n) ? g_deg[c0 + t] : 0;
    if (t < 512) sm[t] = v;
    __syncthreads();
    for (int st = 1; st < 512; st <<= 1) {
        int u = 0;
        if (t < 512 && t >= st) u = sm[t - st];
        __syncthreads();
        if (t < 512) sm[t] += u;
        __syncthreads();
    }
    int incl = (t < 512) ? sm[t] : 0;
    if (t == 511) g_part2[b] = sm[511];
    gridbar(2);
    if (t < 256) sm[t] = (t < NBLK) ? g_part2[t] : 0;
    __syncthreads();
    for (int st = 1; st < 256; st <<= 1) {
        int u = 0;
        if (t < 256 && t >= st) u = sm[t - st];
        __syncthreads();
        if (t < 256) sm[t] += u;
        __syncthreads();
    }
    if (t == 0) bbase = sm[b] - g_part2[b];
    __syncthreads();
    if (t < n) {
        int off = bbase + incl - v;
        g_off[c0 + t] = off;
        g_wp [c0 + t] = off;
    }
    if (gt == 0) g_off[NN] = EE;
    gridbar(3);

    for (long long e = gt; e < EE; e += GSTR) {
        int src = load_index(ei, e, is64);
        int dst = load_index(ei, EE + e, is64);
        int p = atomicAdd(&g_wp[dst], 1);
        g_srcs[p] = src;
    }

    __syncthreads();
    if (t == 0) {
        asm volatile("red.release.gpu.global.add.u32 [%0], 1;" :: "l"(&g_done) : "memory");
        if (b == 0) {
            unsigned x;
            do {
                asm volatile("ld.acquire.gpu.global.u32 %0, [%1];" : "=r"(x) : "l"(&g_done) : "memory");
            } while (x < NBLK);
            for (int i = 0; i < 8; i++) g_bar[i] = 0;
            __threadfence();
            g_done = 0;
        }
    }
}

// ---------------- BN finalize ----------------
__global__ void finalize_k(const float* __restrict__ gamma, const float* __restrict__ beta) {
    int c = threadIdx.x;
    const float invn = 1.f / (float)NN;
    float mean = g_stats[c] * invn;
    float var  = g_stats[256 + c] * invn - mean * mean;
    float sc   = gamma[c] * rsqrtf(var + BN_EPS);
    g_scsh[c]       = sc;
    g_scsh[256 + c] = beta[c] - mean * sc;
}

// ---------------- aggregation -> packed split-bf16 activations ----------------
template<int DIMV, bool BN>
__global__ void agg_k(const float* __restrict__ x, uint32_t* __restrict__ ahi,
                      uint32_t* __restrict__ alo) {
    constexpr int RPB = 256 / DIMV;
    int r = blockIdx.x * RPB + threadIdx.x / DIMV;
    int c = threadIdx.x & (DIMV - 1);
    if (r >= NN) return;
    const float4* x4 = (const float4*)x;
    float4 s = x4[(size_t)r * DIMV + c];
    int i0 = g_off[r], i1 = g_off[r + 1];
    int i = i0;
    for (; i + 4 <= i1; i += 4) {
        int s0 = g_srcs[i], s1 = g_srcs[i + 1], s2 = g_srcs[i + 2], s3 = g_srcs[i + 3];
        float4 v0 = __ldg(&x4[(size_t)s0 * DIMV + c]);
        float4 v1 = __ldg(&x4[(size_t)s1 * DIMV + c]);
        float4 v2 = __ldg(&x4[(size_t)s2 * DIMV + c]);
        float4 v3 = __ldg(&x4[(size_t)s3 * DIMV + c]);
        s.x += v0.x + v1.x + v2.x + v3.x;
        s.y += v0.y + v1.y + v2.y + v3.y;
        s.z += v0.z + v1.z + v2.z + v3.z;
        s.w += v0.w + v1.w + v2.w + v3.w;
    }
    for (; i < i1; i++) {
        float4 v = __ldg(&x4[(size_t)g_srcs[i] * DIMV + c]);
        s.x += v.x; s.y += v.y; s.z += v.z; s.w += v.w;
    }
    if (BN) {
        float cnt = (float)(i1 - i0 + 1);
        float4 sc = ((const float4*)g_scsh)[c];
        float4 sh = ((const float4*)g_scsh)[64 + c];
        s.x = fmaf(sc.x, s.x, cnt * sh.x);
        s.y = fmaf(sc.y, s.y, cnt * sh.y);
        s.z = fmaf(sc.z, s.z, cnt * sh.z);
        s.w = fmaf(sc.w, s.w, cnt * sh.w);
    }
    uint32_t h0, l0, h1, l1;
    split2(s.x, s.y, h0, l0);
    split2(s.z, s.w, h1, l1);
    ((uint2*)ahi)[(size_t)r * DIMV + c] = make_uint2(h0, h1);
    ((uint2*)alo)[(size_t)r * DIMV + c] = make_uint2(l0, l1);
}

// ---------------- bf16x3 tensor GEMM: unified 3-stage cp.async + ldmatrix ----------------
// dynamic smem: 3 stages x 24576B. stage layout (u32): Ahi[128][12] @0, Alo @1536,
// Bhi @3072, Blo @4608. total 73728 B.
#define STGU 6144
#define GSMB 73728

template<int K, bool STATS, bool SPLIT_OUT>
__global__ void __launch_bounds__(256, 2)
gemm_bf(const uint32_t* __restrict__ Ahi, const uint32_t* __restrict__ Alo,
        const uint32_t* __restrict__ Bhi, const uint32_t* __restrict__ Blo,
        const float* __restrict__ bias,
        float* __restrict__ Cf, uint32_t* __restrict__ Chi, uint32_t* __restrict__ Clo) {
    constexpr int NT = K / 16, KP = K / 2;
    extern __shared__ uint32_t dsm[];
    const uint32_t smb = saddr(dsm);

    const int tid  = threadIdx.x;
    const int lane = tid & 31, w = tid >> 5;
    const int wm = (w >> 2) * 64, wn = (w & 3) * 32;
    const int m0 = blockIdx.x * 128, n0 = blockIdx.y * 128;
    const int lq = lane >> 2, lr = lane & 3;
    const int row = tid >> 1, ch = tid & 1;    // loader mapping

    const uint32_t aoffA = ((uint32_t)(wm + (lane & 7) + ((lane >> 3) & 1) * 8) * 12
                            + (uint32_t)(lane >> 4) * 4) * 4;
    const uint32_t aoffB = ((uint32_t)(wn + (lane & 7) + ((lane >> 4) & 1) * 8) * 12
                            + (uint32_t)((lane >> 3) & 1) * 4) * 4;

    float acc[4][4][4];
#pragma unroll
    for (int i = 0; i < 4; i++)
#pragma unroll
        for (int j = 0; j < 4; j++)
#pragma unroll
            for (int r = 0; r < 4; r++) acc[i][j][r] = 0.f;

    auto cpStage = [&](int kt, int st) {
        uint32_t d = smb + (uint32_t)(st * STGU + row * 12 + ch * 4) * 4;
        size_t ao = (size_t)(m0 + row) * KP + kt * 8 + ch * 4;
        size_t bo = (size_t)(n0 + row) * KP + kt * 8 + ch * 4;
        cp16(d,                Ahi + ao);
        cp16(d + 1536 * 4,     Alo + ao);
        cp16(d + 3072 * 4,     Bhi + bo);
        cp16(d + 4608 * 4,     Blo + bo);
    };

    cpStage(0, 0);
    asm volatile("cp.async.commit_group;");
    cpStage(1, 1);
    asm volatile("cp.async.commit_group;");

    int bs = 0;
    for (int kt = 0; kt < NT; kt++) {
        if (kt + 1 < NT) asm volatile("cp.async.wait_group 1;");
        else             asm volatile("cp.async.wait_group 0;");
        __syncthreads();
        if (kt + 2 < NT) {
            int st2 = bs + 2; if (st2 >= 3) st2 -= 3;
            cpStage(kt + 2, st2);
            asm volatile("cp.async.commit_group;");
        }

        uint32_t ah[4][4], al[4][4], bh[4][2], bl[4][2];
        const uint32_t aAh = smb + (uint32_t)(bs * STGU) * 4 + aoffA;
        const uint32_t aBh = smb + (uint32_t)(bs * STGU + 3072) * 4 + aoffB;
#pragma unroll
        for (int mi = 0; mi < 4; mi++) {
            ldsm4(ah[mi], aAh + mi * 768);
            ldsm4(al[mi], aAh + 6144 + mi * 768);
        }
#pragma unroll
        for (int nip = 0; nip < 2; nip++) {
            ldsm4(&bh[2 * nip][0], aBh + nip * 768);
            ldsm4(&bl[2 * nip][0], aBh + 6144 + nip * 768);
        }
#pragma unroll
        for (int mi = 0; mi < 4; mi++)
#pragma unroll
            for (int ni = 0; ni < 4; ni++) {
                mma_bf16(acc[mi][ni], ah[mi], bh[ni]);
                mma_bf16(acc[mi][ni], al[mi], bh[ni]);
                mma_bf16(acc[mi][ni], ah[mi], bl[ni]);
            }
        bs = (bs == 2) ? 0 : bs + 1;
    }

    float cs[8], cq[8];
    if (STATS) {
#pragma unroll
        for (int j = 0; j < 8; j++) { cs[j] = 0.f; cq[j] = 0.f; }
    }

#pragma unroll
    for (int mi = 0; mi < 4; mi++)
#pragma unroll
        for (int half = 0; half < 2; half++) {
            int orow = m0 + wm + mi * 16 + lq + half * 8;
            if (orow < NN) {
#pragma unroll
                for (int ni = 0; ni < 4; ni++) {
                    int col = n0 + wn + ni * 8 + 2 * lr;
                    float2 bv = *(const float2*)&bias[col];
                    float v0 = fmaxf(acc[mi][ni][half * 2 + 0] + bv.x, 0.f);
                    float v1 = fmaxf(acc[mi][ni][half * 2 + 1] + bv.y, 0.f);
                    if (STATS) {
                        cs[ni * 2 + 0] += v0; cq[ni * 2 + 0] += v0 * v0;
                        cs[ni * 2 + 1] += v1; cq[ni * 2 + 1] += v1 * v1;
                    }
                    if (SPLIT_OUT) {
                        uint32_t h, l;
                        split2(v0, v1, h, l);
                        Chi[(size_t)orow * 128 + (col >> 1)] = h;
                        Clo[(size_t)orow * 128 + (col >> 1)] = l;
                    } else {
                        *(float2*)&Cf[(size_t)orow * 256 + col] = make_float2(v0, v1);
                    }
                }
            }
        }

    if (STATS) {
#pragma unroll
        for (int j = 0; j < 8; j++) {
#pragma unroll
            for (int o = 4; o < 32; o <<= 1) {
                cs[j] += __shfl_xor_sync(0xffffffffu, cs[j], o);
                cq[j] += __shfl_xor_sync(0xffffffffu, cq[j], o);
            }
        }
        if (lq == 0) {
#pragma unroll
            for (int j = 0; j < 8; j++) {
                int col = n0 + wn + (j >> 1) * 8 + 2 * lr + (j & 1);
                atomicAdd(&g_stats[col], cs[j]);
                atomicAdd(&g_stats[256 + col], cq[j]);
            }
        }
    }
}

// ---------------- global add pool with fused BN ----------------
__device__ int lower_bound_g(const void* b, int v, int is64) {
    int lo = 0, hi = NN;
    while (lo < hi) {
        int mid = (lo + hi) >> 1;
        if (load_index(b, mid, is64) < v) lo = mid + 1; else hi = mid;
    }
    return lo;
}
__global__ void pool_k(const float* __restrict__ h, const void* __restrict__ batch,
                       float* __restrict__ out) {
    __shared__ int slo, shi;
    int g = blockIdx.x;
    if (threadIdx.x == 0) {
        int is64 = g_idx64;
        slo = lower_bound_g(batch, g, is64);
        shi = lower_bound_g(batch, g + 1, is64);
    }
    __syncthreads();
    int c = threadIdx.x;
    float s = 0.f;
    int r = slo;
    for (; r + 2 <= shi; r += 2)
        s += h[(size_t)r * 256 + c] + h[(size_t)(r + 1) * 256 + c];
    if (r < shi) s += h[(size_t)r * 256 + c];
    out[g * 256 + c] = fmaf(g_scsh[c], s, (float)(shi - slo) * g_scsh[256 + c]);
}

// ---------------- launch ----------------
extern "C" void kernel_launch(void* const* d_in, const int* in_sizes, int n_in,
                              void* d_out, int out_size) {
    const float* x     = (const float*)d_in[0];
    const void*  ei    = d_in[1];
    const void*  batch = d_in[2];

    float *h2, *stats;
    uint32_t *ahi, *alo, *hhi, *hlo, *bhi, *blo;
    cudaGetSymbolAddress((void**)&h2,    g_h2);
    cudaGetSymbolAddress((void**)&stats, g_stats);
    cudaGetSymbolAddress((void**)&ahi,   g_ahi);
    cudaGetSymbolAddress((void**)&alo,   g_alo);
    cudaGetSymbolAddress((void**)&hhi,   g_hhi);
    cudaGetSymbolAddress((void**)&hlo,   g_hlo);
    cudaGetSymbolAddress((void**)&bhi,   g_bhi);
    cudaGetSymbolAddress((void**)&blo,   g_blo);

    cudaFuncSetAttribute(gemm_bf<128, false, true>,
                         cudaFuncAttributeMaxDynamicSharedMemorySize, GSMB);
    cudaFuncSetAttribute(gemm_bf<256, false, true>,
                         cudaFuncAttributeMaxDynamicSharedMemorySize, GSMB);
    cudaFuncSetAttribute(gemm_bf<256, true, false>,
                         cudaFuncAttributeMaxDynamicSharedMemorySize, GSMB);

    convw_all_k<<<705, 256>>>((const float*)d_in[3], (const float*)d_in[5],
                              (const float*)d_in[9], (const float*)d_in[11],
                              (const float*)d_in[15], (const float*)d_in[17],
                              (const int*)ei);
    csr_coop_k<<<NBLK, NTHR>>>(ei);

    agg_k<32, false><<<(NN + 7) / 8, 256>>>(x, ahi, alo);

    const dim3 GB((NN + 127) / 128, 2);
    for (int l = 0; l < 3; l++) {
        const float* b1    = (const float*)d_in[4 + 6 * l];
        const float* b2    = (const float*)d_in[6 + 6 * l];
        const float* gamma = (const float*)d_in[7 + 6 * l];
        const float* beta  = (const float*)d_in[8 + 6 * l];
        const uint32_t* w1h = bhi + (2 * l) * 32768;
        const uint32_t* w1l = blo + (2 * l) * 32768;
        const uint32_t* w2h = bhi + (2 * l + 1) * 32768;
        const uint32_t* w2l = blo + (2 * l + 1) * 32768;

        if (l > 0)
            agg_k<64, true><<<(NN + 3) / 4, 256>>>(h2, ahi, alo);

        if (l == 0)
            gemm_bf<128, false, true><<<GB, 256, GSMB>>>(ahi, alo, w1h, w1l, b1,
                                                         nullptr, hhi, hlo);
        else
            gemm_bf<256, false, true><<<GB, 256, GSMB>>>(ahi, alo, w1h, w1l, b1,
                                                         nullptr, hhi, hlo);

        cudaMemsetAsync(stats, 0, 2 * DD * sizeof(float));
        gemm_bf<256, true, false><<<GB, 256, GSMB>>>(hhi, hlo, w2h, w2l, b2,
                                                     h2, nullptr, nullptr);
        finalize_k<<<1, 256>>>(gamma, beta);
    }

    pool_k<<<GG, 256>>>(h2, batch, (float*)d_out);
}

// round 14
// speedup vs baseline: 1.0462x; 1.0462x over previous
#include <cuda_runtime.h>
#include <cstdint>

#define NN 50000
#define FF 128
#define DD 256
#define EE 800000
#define GG 128
#define BN_EPS 1e-5f
#define NBLK 148
#define NTHR 1024

// ---------------- static scratch ----------------
__device__ float    g_agg[(size_t)NN * DD];
__device__ float    g_hid[(size_t)NN * DD];
__device__ float    g_h2 [(size_t)NN * DD];
__device__ float    g_stats[2 * DD];
__device__ float    g_scsh[2 * DD];
__device__ int      g_idx64;
__device__ uint32_t g_bhi[6 * 256 * 128];
__device__ uint32_t g_blo[6 * 256 * 128];
__device__ int      g_deg[NN];
__device__ int      g_off[NN + 1];
__device__ int      g_wp [NN];
__device__ int      g_srcs[EE];
__device__ int      g_part2[NBLK];
__device__ unsigned g_bar[8];
__device__ unsigned g_done;

// ---------------- helpers ----------------
__device__ __forceinline__ void split2(float e, float o, uint32_t& hi, uint32_t& lo) {
    uint32_t h;
    asm("cvt.rn.bf16x2.f32 %0, %1, %2;" : "=r"(h) : "f"(o), "f"(e));
    float ef = __uint_as_float(h << 16);
    float of = __uint_as_float(h & 0xffff0000u);
    uint32_t l;
    asm("cvt.rn.bf16x2.f32 %0, %1, %2;" : "=r"(l) : "f"(o - of), "f"(e - ef));
    hi = h; lo = l;
}
__device__ __forceinline__ void mma_bf16(float* d, const uint32_t* a, const uint32_t* b) {
    asm volatile("mma.sync.aligned.m16n8k16.row.col.f32.bf16.bf16.f32 "
                 "{%0,%1,%2,%3}, {%4,%5,%6,%7}, {%8,%9}, {%0,%1,%2,%3};"
                 : "+f"(d[0]), "+f"(d[1]), "+f"(d[2]), "+f"(d[3])
                 : "r"(a[0]), "r"(a[1]), "r"(a[2]), "r"(a[3]), "r"(b[0]), "r"(b[1]));
}
__device__ __forceinline__ void ldsm4(uint32_t* r, uint32_t a) {
    asm volatile("ldmatrix.sync.aligned.m8n8.x4.shared.b16 {%0,%1,%2,%3}, [%4];"
                 : "=r"(r[0]), "=r"(r[1]), "=r"(r[2]), "=r"(r[3]) : "r"(a));
}
__device__ __forceinline__ void cp16(uint32_t dst, const void* src) {
    asm volatile("cp.async.cg.shared.global [%0], [%1], 16;" :: "r"(dst), "l"(src));
}
__device__ __forceinline__ uint32_t saddr(const void* p) {
    return (uint32_t)__cvta_generic_to_shared(p);
}
__device__ __forceinline__ int load_index(const void* p, long long i, int is64) {
    if (is64) return (int)((const long long*)p)[i];
    return ((const int*)p)[i];
}
__device__ __forceinline__ void gridbar(int i) {
    __syncthreads();
    if (threadIdx.x == 0) {
        unsigned* ctr = &g_bar[i];
        asm volatile("red.release.gpu.global.add.u32 [%0], 1;" :: "l"(ctr) : "memory");
        unsigned x;
        do {
            asm volatile("ld.acquire.gpu.global.u32 %0, [%1];" : "=r"(x) : "l"(ctr) : "memory");
        } while (x < NBLK);
    }
    __syncthreads();
}

// weight pre-split work item: t in [0, 180224)
__device__ __forceinline__ void convw_item(int t, const float* w0, const float* w1,
                                           const float* w2, const float* w3,
                                           const float* w4, const float* w5) {
    const float* w; int kpc, loc, slot;
    if (t < 16384) { slot = 0; kpc = 64; loc = t; w = w0; }
    else {
        slot = 1 + (t - 16384) / 32768;
        loc  = (t - 16384) % 32768;
        kpc  = 128;
        w = (slot == 1) ? w1 : (slot == 2) ? w2 : (slot == 3) ? w3 : (slot == 4) ? w4 : w5;
    }
    int n = loc / kpc, kp = loc - n * kpc;
    float e = w[(2 * kp)     * 256 + n];
    float o = w[(2 * kp + 1) * 256 + n];
    uint32_t h, l;
    split2(e, o, h, l);
    g_bhi[slot * 32768 + n * kpc + kp] = h;
    g_blo[slot * 32768 + n * kpc + kp] = l;
}

// ---------------- 1: CSR build + weight split (cooperative) ----------------
__global__ void __launch_bounds__(NTHR)
csr_coop_k(const void* ei, const float* w0, const float* w1, const float* w2,
           const float* w3, const float* w4, const float* w5) {
    __shared__ int sm[512];
    __shared__ int bbase;
    const int b = blockIdx.x, t = threadIdx.x;
    const int gt = b * NTHR + t;
    const int GSTR = NBLK * NTHR;

    // phase A: zero degrees + weight pre-split + idx dtype detect
    for (int i = gt; i < NN; i += GSTR) g_deg[i] = 0;
    for (int i = gt; i < 180224; i += GSTR) convw_item(i, w0, w1, w2, w3, w4, w5);
    if (gt == 0) {
        const int* e32 = (const int*)ei;
        int allz = 1;
        for (int j = 1; j < 512; j += 2)
            if (e32[j] != 0) { allz = 0; break; }
        g_idx64 = allz;
    }
    gridbar(0);
    const int is64 = g_idx64;

    // phase B: degree histogram
    for (long long e = gt; e < EE; e += GSTR) {
        int dst = load_index(ei, EE + e, is64);
        atomicAdd(&g_deg[dst], 1);
    }
    gridbar(1);

    // phase C: scan
    const int CH = (NN + NBLK - 1) / NBLK;
    const int c0 = b * CH;
    const int n  = min(NN, c0 + CH) - c0;
    int v = (t < n) ? g_deg[c0 + t] : 0;
    if (t < 512) sm[t] = v;
    __syncthreads();
    for (int st = 1; st < 512; st <<= 1) {
        int u = 0;
        if (t < 512 && t >= st) u = sm[t - st];
        __syncthreads();
        if (t < 512) sm[t] += u;
        __syncthreads();
    }
    int incl = (t < 512) ? sm[t] : 0;
    if (t == 511) g_part2[b] = sm[511];
    gridbar(2);
    if (t < 256) sm[t] = (t < NBLK) ? g_part2[t] : 0;
    __syncthreads();
    for (int st = 1; st < 256; st <<= 1) {
        int u = 0;
        if (t < 256 && t >= st) u = sm[t - st];
        __syncthreads();
        if (t < 256) sm[t] += u;
        __syncthreads();
    }
    if (t == 0) bbase = sm[b] - g_part2[b];
    __syncthreads();
    if (t < n) {
        int off = bbase + incl - v;
        g_off[c0 + t] = off;
        g_wp [c0 + t] = off;
    }
    if (gt == 0) g_off[NN] = EE;
    gridbar(3);

    // phase D: fill
    for (long long e = gt; e < EE; e += GSTR) {
        int src = load_index(ei, e, is64);
        int dst = load_index(ei, EE + e, is64);
        int p = atomicAdd(&g_wp[dst], 1);
        g_srcs[p] = src;
    }

    // reset barrier counters for next graph replay
    __syncthreads();
    if (t == 0) {
        asm volatile("red.release.gpu.global.add.u32 [%0], 1;" :: "l"(&g_done) : "memory");
        if (b == 0) {
            unsigned x;
            do {
                asm volatile("ld.acquire.gpu.global.u32 %0, [%1];" : "=r"(x) : "l"(&g_done) : "memory");
            } while (x < NBLK);
            for (int i = 0; i < 8; i++) g_bar[i] = 0;
            __threadfence();
            g_done = 0;
        }
    }
}

// ---------------- BN finalize ----------------
__global__ void finalize_k(const float* __restrict__ gamma, const float* __restrict__ beta) {
    int c = threadIdx.x;
    const float invn = 1.f / (float)NN;
    float mean = g_stats[c] * invn;
    float var  = g_stats[256 + c] * invn - mean * mean;
    float sc   = gamma[c] * rsqrtf(var + BN_EPS);
    g_scsh[c]       = sc;
    g_scsh[256 + c] = beta[c] - mean * sc;
}

// ---------------- aggregation (fp32 out, fused prev-layer BN) ----------------
template<int DIMV, bool BN>
__global__ void agg_k(const float* __restrict__ x, float* __restrict__ agg) {
    constexpr int RPB = 256 / DIMV;
    int r = blockIdx.x * RPB + threadIdx.x / DIMV;
    int c = threadIdx.x & (DIMV - 1);
    if (r >= NN) return;
    const float4* x4 = (const float4*)x;
    float4 s = x4[(size_t)r * DIMV + c];
    int i0 = g_off[r], i1 = g_off[r + 1];
    int i = i0;
    for (; i + 4 <= i1; i += 4) {
        int s0 = g_srcs[i], s1 = g_srcs[i + 1], s2 = g_srcs[i + 2], s3 = g_srcs[i + 3];
        float4 v0 = __ldg(&x4[(size_t)s0 * DIMV + c]);
        float4 v1 = __ldg(&x4[(size_t)s1 * DIMV + c]);
        float4 v2 = __ldg(&x4[(size_t)s2 * DIMV + c]);
        float4 v3 = __ldg(&x4[(size_t)s3 * DIMV + c]);
        s.x += v0.x + v1.x + v2.x + v3.x;
        s.y += v0.y + v1.y + v2.y + v3.y;
        s.z += v0.z + v1.z + v2.z + v3.z;
        s.w += v0.w + v1.w + v2.w + v3.w;
    }
    for (; i < i1; i++) {
        float4 v = __ldg(&x4[(size_t)g_srcs[i] * DIMV + c]);
        s.x += v.x; s.y += v.y; s.z += v.z; s.w += v.w;
    }
    if (BN) {
        float cnt = (float)(i1 - i0 + 1);
        float4 sc = ((const float4*)g_scsh)[c];
        float4 sh = ((const float4*)g_scsh)[64 + c];
        s.x = fmaf(sc.x, s.x, cnt * sh.x);
        s.y = fmaf(sc.y, s.y, cnt * sh.y);
        s.z = fmaf(sc.z, s.z, cnt * sh.z);
        s.w = fmaf(sc.w, s.w, cnt * sh.w);
    }
    ((float4*)agg)[(size_t)r * DIMV + c] = s;
}

// ---------------- bf16x3 tensor GEMM (R10-proven: ldmatrix + 2-stage A + 3-stage B) ----------------
// dynamic smem (bytes): A_hi[2][128][12]u32 @0, A_lo @12288, B_hi[3][128][12] @24576,
// B_lo[3] @43008. total 61440.
#define GSMB 61440

template<int K, bool STATS>
__global__ void __launch_bounds__(256, 2)
gemm_bf(const float* __restrict__ A, const uint32_t* __restrict__ Bhi,
        const uint32_t* __restrict__ Blo, const float* __restrict__ bias,
        float* __restrict__ C) {
    constexpr int NT = K / 16, KP = K / 2;
    extern __shared__ uint32_t dsm[];
    const uint32_t smb = saddr(dsm);

    const int tid  = threadIdx.x;
    const int lane = tid & 31, w = tid >> 5;
    const int wm = (w >> 2) * 64, wn = (w & 3) * 32;
    const int m0 = blockIdx.x * 128, n0 = blockIdx.y * 128;
    const int lq = lane >> 2, lr = lane & 3;
    const int arow = tid >> 1, akh = tid & 1;
    const bool avalid = (m0 + arow) < NN;

    const uint32_t aoffA = ((uint32_t)(wm + (lane & 7) + ((lane >> 3) & 1) * 8) * 12
                            + (uint32_t)(lane >> 4) * 4) * 4;
    const uint32_t aoffB = ((uint32_t)(wn + (lane & 7) + ((lane >> 4) & 1) * 8) * 12
                            + (uint32_t)((lane >> 3) & 1) * 4) * 4;

    float acc[4][4][4];
#pragma unroll
    for (int i = 0; i < 4; i++)
#pragma unroll
        for (int j = 0; j < 4; j++)
#pragma unroll
            for (int r = 0; r < 4; r++) acc[i][j][r] = 0.f;

    float rA[8];
    auto ldgA = [&](int kt) {
        if (avalid) {
            const float4* p = (const float4*)(A + (size_t)(m0 + arow) * K + kt * 16 + akh * 8);
            float4 v0 = __ldg(p), v1 = __ldg(p + 1);
            rA[0] = v0.x; rA[1] = v0.y; rA[2] = v0.z; rA[3] = v0.w;
            rA[4] = v1.x; rA[5] = v1.y; rA[6] = v1.z; rA[7] = v1.w;
        } else {
#pragma unroll
            for (int j = 0; j < 8; j++) rA[j] = 0.f;
        }
    };
    auto stsA = [&](int st) {
        uint32_t h[4], l[4];
#pragma unroll
        for (int j = 0; j < 4; j++) split2(rA[2 * j], rA[2 * j + 1], h[j], l[j]);
        int idx = st * 1536 + arow * 12 + akh * 4;
        *(uint4*)&dsm[idx]        = make_uint4(h[0], h[1], h[2], h[3]);
        *(uint4*)&dsm[idx + 3072] = make_uint4(l[0], l[1], l[2], l[3]);
    };
    auto cpB = [&](int kt, int st) {
        size_t o = (size_t)(n0 + arow) * KP + kt * 8 + akh * 4;
        uint32_t d = smb + 24576 + st * 6144 + (uint32_t)(arow * 12 + akh * 4) * 4;
        cp16(d, Bhi + o);
        cp16(d + 18432, Blo + o);
    };

    // prologue
    ldgA(0);
    cpB(0, 0);
    asm volatile("cp.async.commit_group;");
    cpB(1, 1);
    asm volatile("cp.async.commit_group;");
    stsA(0);
    ldgA(1);

    int bs = 0;
    for (int kt = 0; kt < NT; kt++) {
        const int sa = kt & 1;
        if (kt + 1 < NT) asm volatile("cp.async.wait_group 1;");
        else             asm volatile("cp.async.wait_group 0;");
        __syncthreads();
        if (kt + 2 < NT) {
            int bs2 = bs + 2; if (bs2 >= 3) bs2 -= 3;
            cpB(kt + 2, bs2);
            asm volatile("cp.async.commit_group;");
        }
        if (kt + 1 < NT) {
            stsA(sa ^ 1);
            if (kt + 2 < NT) ldgA(kt + 2);
        }

        uint32_t ah[4][4], al[4][4], bh[4][2], bl[4][2];
        const uint32_t aAh = smb + sa * 6144 + aoffA;
        const uint32_t aBh = smb + 24576 + bs * 6144 + aoffB;
#pragma unroll
        for (int mi = 0; mi < 4; mi++) {
            ldsm4(ah[mi], aAh + mi * 768);
            ldsm4(al[mi], aAh + 12288 + mi * 768);
        }
#pragma unroll
        for (int nip = 0; nip < 2; nip++) {
            ldsm4(&bh[2 * nip][0], aBh + nip * 768);
            ldsm4(&bl[2 * nip][0], aBh + 18432 + nip * 768);
        }
#pragma unroll
        for (int mi = 0; mi < 4; mi++)
#pragma unroll
            for (int ni = 0; ni < 4; ni++) {
                mma_bf16(acc[mi][ni], ah[mi], bh[ni]);
                mma_bf16(acc[mi][ni], al[mi], bh[ni]);
                mma_bf16(acc[mi][ni], ah[mi], bl[ni]);
            }
        bs = (bs == 2) ? 0 : bs + 1;
    }

    float cs[8], cq[8];
    if (STATS) {
#pragma unroll
        for (int j = 0; j < 8; j++) { cs[j] = 0.f; cq[j] = 0.f; }
    }

#pragma unroll
    for (int mi = 0; mi < 4; mi++)
#pragma unroll
        for (int half = 0; half < 2; half++) {
            int row = m0 + wm + mi * 16 + lq + half * 8;
            if (row < NN) {
#pragma unroll
                for (int ni = 0; ni < 4; ni++) {
                    int col = n0 + wn + ni * 8 + 2 * lr;
                    float2 bv = *(const float2*)&bias[col];
                    float v0 = fmaxf(acc[mi][ni][half * 2 + 0] + bv.x, 0.f);
                    float v1 = fmaxf(acc[mi][ni][half * 2 + 1] + bv.y, 0.f);
                    if (STATS) {
                        cs[ni * 2 + 0] += v0; cq[ni * 2 + 0] += v0 * v0;
                        cs[ni * 2 + 1] += v1; cq[ni * 2 + 1] += v1 * v1;
                    }
                    *(float2*)&C[(size_t)row * 256 + col] = make_float2(v0, v1);
                }
            }
        }

    if (STATS) {
#pragma unroll
        for (int j = 0; j < 8; j++) {
#pragma unroll
            for (int o = 4; o < 32; o <<= 1) {
                cs[j] += __shfl_xor_sync(0xffffffffu, cs[j], o);
                cq[j] += __shfl_xor_sync(0xffffffffu, cq[j], o);
            }
        }
        if (lq == 0) {
#pragma unroll
            for (int j = 0; j < 8; j++) {
                int col = n0 + wn + (j >> 1) * 8 + 2 * lr + (j & 1);
                atomicAdd(&g_stats[col], cs[j]);
                atomicAdd(&g_stats[256 + col], cq[j]);
            }
        }
    }
}

// ---------------- global add pool with fused BN ----------------
__device__ int lower_bound_g(const void* b, int v, int is64) {
    int lo = 0, hi = NN;
    while (lo < hi) {
        int mid = (lo + hi) >> 1;
        if (load_index(b, mid, is64) < v) lo = mid + 1; else hi = mid;
    }
    return lo;
}
__global__ void pool_k(const float* __restrict__ h, const void* __restrict__ batch,
                       float* __restrict__ out) {
    __shared__ int slo, shi;
    int g = blockIdx.x;
    if (threadIdx.x == 0) {
        int is64 = g_idx64;
        slo = lower_bound_g(batch, g, is64);
        shi = lower_bound_g(batch, g + 1, is64);
    }
    __syncthreads();
    int c = threadIdx.x;
    float s = 0.f;
    int r = slo;
    for (; r + 2 <= shi; r += 2)
        s += h[(size_t)r * 256 + c] + h[(size_t)(r + 1) * 256 + c];
    if (r < shi) s += h[(size_t)r * 256 + c];
    out[g * 256 + c] = fmaf(g_scsh[c], s, (float)(shi - slo) * g_scsh[256 + c]);
}

// ---------------- launch ----------------
extern "C" void kernel_launch(void* const* d_in, const int* in_sizes, int n_in,
                              void* d_out, int out_size) {
    const float* x     = (const float*)d_in[0];
    const void*  ei    = d_in[1];
    const void*  batch = d_in[2];

    float *agg, *hid, *h2, *stats;
    uint32_t *bhi, *blo;
    cudaGetSymbolAddress((void**)&agg,   g_agg);
    cudaGetSymbolAddress((void**)&hid,   g_hid);
    cudaGetSymbolAddress((void**)&h2,    g_h2);
    cudaGetSymbolAddress((void**)&stats, g_stats);
    cudaGetSymbolAddress((void**)&bhi,   g_bhi);
    cudaGetSymbolAddress((void**)&blo,   g_blo);

    cudaFuncSetAttribute(gemm_bf<128, false>,
                         cudaFuncAttributeMaxDynamicSharedMemorySize, GSMB);
    cudaFuncSetAttribute(gemm_bf<256, false>,
                         cudaFuncAttributeMaxDynamicSharedMemorySize, GSMB);
    cudaFuncSetAttribute(gemm_bf<256, true>,
                         cudaFuncAttributeMaxDynamicSharedMemorySize, GSMB);

    // 1: CSR build + weight pre-split (one cooperative kernel)
    csr_coop_k<<<NBLK, NTHR>>>(ei, (const float*)d_in[3], (const float*)d_in[5],
                               (const float*)d_in[9], (const float*)d_in[11],
                               (const float*)d_in[15], (const float*)d_in[17]);

    // 2: layer-0 aggregation.  3: gemm128.  4 (profiled): gemm256+STATS.
    agg_k<32, false><<<(NN + 7) / 8, 256>>>(x, agg);

    const dim3 GB((NN + 127) / 128, 2);
    for (int l = 0; l < 3; l++) {
        const float* b1    = (const float*)d_in[4 + 6 * l];
        const float* b2    = (const float*)d_in[6 + 6 * l];
        const float* gamma = (const float*)d_in[7 + 6 * l];
        const float* beta  = (const float*)d_in[8 + 6 * l];
        const uint32_t* w1h = bhi + (2 * l) * 32768;
        const uint32_t* w1l = blo + (2 * l) * 32768;
        const uint32_t* w2h = bhi + (2 * l + 1) * 32768;
        const uint32_t* w2l = blo + (2 * l + 1) * 32768;

        if (l > 0)
            agg_k<64, true><<<(NN + 3) / 4, 256>>>(h2, agg);

        if (l == 0) gemm_bf<128, false><<<GB, 256, GSMB>>>(agg, w1h, w1l, b1, hid);
        else        gemm_bf<256, false><<<GB, 256, GSMB>>>(agg, w1h, w1l, b1, hid);

        cudaMemsetAsync(stats, 0, 2 * DD * sizeof(float));
        gemm_bf<256, true><<<GB, 256, GSMB>>>(hid, w2h, w2l, b2, h2);
        finalize_k<<<1, 256>>>(gamma, beta);
    }

    pool_k<<<GG, 256>>>(h2, batch, (float*)d_out);
}